// round 13
// baseline (speedup 1.0000x reference)
#include <cuda_runtime.h>
#include <cuda_bf16.h>
#include <mma.h>
#include <cstdint>

using namespace nvcuda;

// B=8, S=512, D=768, R=128
//   P = E @ [Wd;Wz]^T ; distances[b,i,j] = nd_i + nd_j - 2<Pd_i,Pd_j>; depths = ||Pz||^2
// WMMA bf16 m16n16k16 (plain sm_103 target: no tcgen05).
// gemm1: 2-term split (Eh*Wh + Eh*Wl) with in-kernel fp32->bf16 conversion
//        (no prepass kernel). gemm2: 2-term, symmetric (20/32 tiles + mirror).
// Combined rel err ~4e-4 < 1e-3 threshold.

static constexpr int Bn = 8;
static constexpr int Sn = 512;
static constexpr int Dn = 768;
static constexpr int Mtot = Bn * Sn;      // 4096

// Scratch
__device__ __align__(256) __nv_bfloat16 g_Phi[Mtot * 128]; // dist projection hi
__device__ __align__(256) __nv_bfloat16 g_Plo[Mtot * 128]; // dist projection lo
__device__ float g_nd[Mtot];

__device__ __forceinline__ uint32_t smem_u32(const void* p) {
    return (uint32_t)__cvta_generic_to_shared(p);
}
__device__ __forceinline__ void cp16(uint32_t dst, const void* src) {
    asm volatile("cp.async.cg.shared.global [%0], [%1], 16;"
                 :: "r"(dst), "l"(__cvta_generic_to_global(src)) : "memory");
}
__device__ __forceinline__ void cp_commit() {
    asm volatile("cp.async.commit_group;" ::: "memory");
}
template <int N> __device__ __forceinline__ void cp_wait() {
    asm volatile("cp.async.wait_group %0;" :: "n"(N) : "memory");
}
__device__ __forceinline__ void split2(float a, float b, uint32_t& h2, uint32_t& l2) {
    __nv_bfloat16 ha = __float2bfloat16(a), hb = __float2bfloat16(b);
    float ra = a - __bfloat162float(ha);
    float rb = b - __bfloat162float(hb);
    __nv_bfloat16 la = __float2bfloat16(ra), lb = __float2bfloat16(rb);
    h2 = (uint32_t)__bfloat16_as_ushort(ha) | ((uint32_t)__bfloat16_as_ushort(hb) << 16);
    l2 = (uint32_t)__bfloat16_as_ushort(la) | ((uint32_t)__bfloat16_as_ushort(lb) << 16);
}
__device__ __forceinline__ uint32_t pack_hi2(float a, float b) {
    return (uint32_t)__bfloat16_as_ushort(__float2bfloat16(a)) |
           ((uint32_t)__bfloat16_as_ushort(__float2bfloat16(b)) << 16);
}

typedef wmma::fragment<wmma::matrix_a, 16, 16, 16, __nv_bfloat16, wmma::row_major> FragA;
typedef wmma::fragment<wmma::matrix_b, 16, 16, 16, __nv_bfloat16, wmma::col_major> FragB;
typedef wmma::fragment<wmma::accumulator, 16, 16, 16, float> FragC;

// ---------------------------------------------------------------------------
// GEMM1: BM=64, BN=128, BK=64, 256 threads (8 warps 2x4, warp tile 32x32).
// fp32 E/W staged via cp.async (padded 68-float rows), converted in-smem to
// bf16 (A: hi; B: hi+lo) each chunk. 2-term MMA. grid = (2 [dist|depth], 64).
// Epilogue: row norms + Phi/Plo split (dist) / depths (depth) inline.
// Per-buffer smem layout (bytes):
//   Af32 [0,17408)  Bf32 [17408,52224)  Ahi [52224,61440)
//   Bh   [61440,79872)  Bl [79872,98304)      buffer stride 98304, x2 buffers
// ---------------------------------------------------------------------------
static constexpr int P1 = 72;            // bf16 lda
static constexpr int PF = 68;            // fp32 staging lda (bank spread + 16B align)
static constexpr int OFF_BF32 = 17408;
static constexpr int OFF_AHI  = 52224;
static constexpr int OFF_BH   = 61440;
static constexpr int OFF_BL   = 79872;
static constexpr int BUFSTR   = 98304;
static constexpr int SMEM1    = 2 * BUFSTR;   // 196608 B

__global__ __launch_bounds__(256, 1) void gemm1_k(const float* __restrict__ E,
                                                  const float* __restrict__ Wd,
                                                  const float* __restrict__ Wz,
                                                  float* __restrict__ depths_out) {
    extern __shared__ __align__(16) char sm[];
    const uint32_t sb = smem_u32(sm);

    const int tid = threadIdx.x;
    const int wid = tid >> 5;
    const int wm = wid >> 2, wn = wid & 3;
    const int nt = blockIdx.x;           // 0: dist (Wd), 1: depth (Wz)
    const int m0 = blockIdx.y * 64;
    const float* __restrict__ Wsrc = nt ? Wz : Wd;

    // cp.async thread mappings
    const int ar = tid >> 2, ac4 = (tid & 3) * 16;   // A: 64 rows, 4 f4/thread
    const int br = tid >> 1, bc8 = (tid & 1) * 32;   // B: 128 rows, 8 f4/thread

    auto load_chunk = [&](int c, int buf) {
        const int k0 = c * 64;
        const uint32_t bb = sb + buf * BUFSTR;
#pragma unroll
        for (int q = 0; q < 4; q++)                  // A fp32: 64x64
            cp16(bb + (uint32_t)(ar * PF + ac4 + q * 4) * 4,
                 E + (size_t)(m0 + ar) * Dn + k0 + ac4 + q * 4);
#pragma unroll
        for (int q = 0; q < 8; q++)                  // B fp32: 128x64
            cp16(bb + OFF_BF32 + (uint32_t)(br * PF + bc8 + q * 4) * 4,
                 Wsrc + (size_t)br * Dn + k0 + bc8 + q * 4);
        cp_commit();
    };

    // convert thread mappings (bank-conflict-free via PF=68 row spread)
    const int car = tid & 63, cac = (tid >> 6) * 16;  // A: 16 floats/thread
    const int cbr = tid & 127, cbc = (tid >> 7) * 32; // B: 32 floats/thread

    auto convert_chunk = [&](int buf) {
        const char* bufp = sm + buf * BUFSTR;
        // A -> hi only
        {
            const float4* src = (const float4*)(bufp + (size_t)(car * PF + cac) * 4);
            uint32_t h[8];
#pragma unroll
            for (int q = 0; q < 4; q++) {
                float4 v = src[q];
                h[2 * q]     = pack_hi2(v.x, v.y);
                h[2 * q + 1] = pack_hi2(v.z, v.w);
            }
            uint4* dst = (uint4*)(bufp + OFF_AHI + (size_t)(car * P1 + cac) * 2);
            dst[0] = make_uint4(h[0], h[1], h[2], h[3]);
            dst[1] = make_uint4(h[4], h[5], h[6], h[7]);
        }
        // B -> hi + lo
        {
            const float4* src = (const float4*)(bufp + OFF_BF32 + (size_t)(cbr * PF + cbc) * 4);
            uint32_t h[16], l[16];
#pragma unroll
            for (int q = 0; q < 8; q++) {
                float4 v = src[q];
                split2(v.x, v.y, h[2 * q], l[2 * q]);
                split2(v.z, v.w, h[2 * q + 1], l[2 * q + 1]);
            }
            uint4* dh = (uint4*)(bufp + OFF_BH + (size_t)(cbr * P1 + cbc) * 2);
            uint4* dl = (uint4*)(bufp + OFF_BL + (size_t)(cbr * P1 + cbc) * 2);
#pragma unroll
            for (int q = 0; q < 4; q++) {
                dh[q] = make_uint4(h[4 * q], h[4 * q + 1], h[4 * q + 2], h[4 * q + 3]);
                dl[q] = make_uint4(l[4 * q], l[4 * q + 1], l[4 * q + 2], l[4 * q + 3]);
            }
        }
    };

    FragC acc[2][2];
#pragma unroll
    for (int i = 0; i < 2; i++)
#pragma unroll
        for (int j = 0; j < 2; j++) wmma::fill_fragment(acc[i][j], 0.0f);

    load_chunk(0, 0);
    for (int c = 0; c < 12; c++) {
        const int buf = c & 1;
        if (c < 11) { load_chunk(c + 1, buf ^ 1); cp_wait<1>(); }
        else cp_wait<0>();
        __syncthreads();
        convert_chunk(buf);
        __syncthreads();

        const __nv_bfloat16* Ah = (const __nv_bfloat16*)(sm + buf * BUFSTR + OFF_AHI);
        const __nv_bfloat16* Bh = (const __nv_bfloat16*)(sm + buf * BUFSTR + OFF_BH);
        const __nv_bfloat16* Bl = (const __nv_bfloat16*)(sm + buf * BUFSTR + OFF_BL);
#pragma unroll
        for (int kk = 0; kk < 64; kk += 16) {
            FragA ah[2];
            FragB bh[2], bl[2];
#pragma unroll
            for (int f = 0; f < 2; f++) {
                wmma::load_matrix_sync(ah[f], Ah + (wm * 32 + f * 16) * P1 + kk, P1);
                const int n = wn * 32 + f * 16;
                wmma::load_matrix_sync(bh[f], Bh + n * P1 + kk, P1);
                wmma::load_matrix_sync(bl[f], Bl + n * P1 + kk, P1);
            }
#pragma unroll
            for (int i = 0; i < 2; i++)
#pragma unroll
                for (int j = 0; j < 2; j++) {
                    wmma::mma_sync(acc[i][j], ah[i], bh[j], acc[i][j]);
                    wmma::mma_sync(acc[i][j], ah[i], bl[j], acc[i][j]);
                }
        }
        __syncthreads();
    }

    // Epilogue: stage fp32 tile, norms + split (dist) / depths (depth)
    float* Csm = (float*)sm;                         // [64][136]
#pragma unroll
    for (int i = 0; i < 2; i++)
#pragma unroll
        for (int j = 0; j < 2; j++)
            wmma::store_matrix_sync(Csm + (wm * 32 + i * 16) * 136 + wn * 32 + j * 16,
                                    acc[i][j], 136, wmma::mem_row_major);
    __syncthreads();

    const int row = tid >> 2;            // 0..63
    const int part = tid & 3;            // 32-col quarter
    const float* cr = Csm + row * 136 + part * 32;
    float4 vv[8];
    float norm = 0.0f;
#pragma unroll
    for (int q = 0; q < 8; q++) {
        vv[q] = ((const float4*)cr)[q];
        norm += vv[q].x * vv[q].x + vv[q].y * vv[q].y +
                vv[q].z * vv[q].z + vv[q].w * vv[q].w;
    }
    norm += __shfl_xor_sync(0xffffffffu, norm, 1);
    norm += __shfl_xor_sync(0xffffffffu, norm, 2);

    const int grow = m0 + row;
    if (nt == 0) {
        uint2* dh = (uint2*)(g_Phi + (size_t)grow * 128 + part * 32);
        uint2* dl = (uint2*)(g_Plo + (size_t)grow * 128 + part * 32);
#pragma unroll
        for (int q = 0; q < 8; q++) {
            uint32_t h0, l0, h1, l1;
            split2(vv[q].x, vv[q].y, h0, l0);
            split2(vv[q].z, vv[q].w, h1, l1);
            dh[q] = make_uint2(h0, h1);
            dl[q] = make_uint2(l0, l1);
        }
        if (part == 0) g_nd[grow] = norm;
    } else {
        if (part == 0) depths_out[grow] = norm;
    }
}

// ---------------------------------------------------------------------------
// GEMM2: per-batch Gram (2-term) + distance epilogue, SYMMETRIC.
// Tiles (mi of 8 [64 rows], nj of 4 [128 cols]) with mi <= 2*nj+1: 20 tiles.
// Tiles with mi < 2*nj additionally write the mirrored region (transposed).
// BM=64, BN=128, BK=64 x2 dbl-buffered; grid = (20, 1, 8) = 160 CTAs, occ 2.
// ---------------------------------------------------------------------------
static constexpr int P2 = 72;
static constexpr int A2SZ = 64 * P2;                 // A hi only
static constexpr int B2SZ = 128 * P2;
static constexpr int BUF2 = A2SZ + 2 * B2SZ;         // 23040 elems
static constexpr int SMEM2 = 2 * BUF2 * 2;           // 92160 B

__global__ __launch_bounds__(256, 2) void gemm2_k(float* __restrict__ out) {
    extern __shared__ __align__(16) char sm[];
    __nv_bfloat16* base = (__nv_bfloat16*)sm;
    __shared__ float ndi_s[64];
    __shared__ float ndj_s[128];

    const int tid = threadIdx.x;
    const int wid = tid >> 5;
    const int wm = wid >> 2, wn = wid & 3;
    const int b = blockIdx.z;

    // tile index -> (mi, nj): nj groups of size 2,4,6,8 (cum 2,6,12,20)
    const int x = blockIdx.x;
    const int nj = (x < 2) ? 0 : (x < 6) ? 1 : (x < 12) ? 2 : 3;
    const int mi = x - ((nj == 0) ? 0 : (nj == 1) ? 2 : (nj == 2) ? 6 : 12);
    const int m0 = mi * 64;
    const int n0 = nj * 128;
    const size_t pbase = (size_t)b * Sn * 128;

    const float* __restrict__ ndb = g_nd + (size_t)b * Sn;
    if (tid < 64) ndi_s[tid] = ndb[m0 + tid];
    else if (tid < 192) ndj_s[tid - 64] = ndb[n0 + tid - 64];

    const int qrow = tid >> 3, qc8 = (tid & 7) * 8;

    auto load_chunk = [&](int c, int buf) {
        const int k0 = c * 64;
        __nv_bfloat16* Ah = base + buf * BUF2;
        __nv_bfloat16* Bh = Ah + A2SZ;
        __nv_bfloat16* Bl = Bh + B2SZ;
        const uint32_t sAh = smem_u32(Ah), sBh = smem_u32(Bh), sBl = smem_u32(Bl);
#pragma unroll
        for (int i = 0; i < 2; i++) {                // A: 64 rows (hi only)
            const int r = qrow + i * 32;
            const uint32_t d = (uint32_t)(r * P2 + qc8) * 2;
            cp16(sAh + d, g_Phi + pbase + (size_t)(m0 + r) * 128 + k0 + qc8);
        }
#pragma unroll
        for (int i = 0; i < 4; i++) {                // B: 128 rows hi+lo
            const int r = qrow + i * 32;
            const uint32_t d = (uint32_t)(r * P2 + qc8) * 2;
            const size_t s = pbase + (size_t)(n0 + r) * 128 + k0 + qc8;
            cp16(sBh + d, g_Phi + s);
            cp16(sBl + d, g_Plo + s);
        }
        cp_commit();
    };

    FragC acc[2][2];
#pragma unroll
    for (int i = 0; i < 2; i++)
#pragma unroll
        for (int j = 0; j < 2; j++) wmma::fill_fragment(acc[i][j], 0.0f);

    load_chunk(0, 0);
    for (int c = 0; c < 2; c++) {
        if (c < 1) { load_chunk(1, 1); cp_wait<1>(); }
        else cp_wait<0>();
        __syncthreads();

        const __nv_bfloat16* Ah = base + (c & 1) * BUF2;
        const __nv_bfloat16* Bh = Ah + A2SZ;
        const __nv_bfloat16* Bl = Bh + B2SZ;
#pragma unroll
        for (int kk = 0; kk < 64; kk += 16) {
            FragA ah[2];
            FragB bh[2], bl[2];
#pragma unroll
            for (int f = 0; f < 2; f++) {
                wmma::load_matrix_sync(ah[f], Ah + (wm * 32 + f * 16) * P2 + kk, P2);
                const int n = wn * 32 + f * 16;
                wmma::load_matrix_sync(bh[f], Bh + n * P2 + kk, P2);
                wmma::load_matrix_sync(bl[f], Bl + n * P2 + kk, P2);
            }
#pragma unroll
            for (int i = 0; i < 2; i++)
#pragma unroll
                for (int j = 0; j < 2; j++) {
                    wmma::mma_sync(acc[i][j], ah[i], bh[j], acc[i][j]);
                    wmma::mma_sync(acc[i][j], ah[i], bl[j], acc[i][j]);
                }
        }
        __syncthreads();
    }

    // Stage fp32 Gram, fused distance epilogue (direct tile)
    float* Csm = (float*)sm;                              // [64][136]
#pragma unroll
    for (int i = 0; i < 2; i++)
#pragma unroll
        for (int j = 0; j < 2; j++)
            wmma::store_matrix_sync(Csm + (wm * 32 + i * 16) * 136 + wn * 32 + j * 16,
                                    acc[i][j], 136, wmma::mem_row_major);
    __syncthreads();

    {
        const int row = tid >> 2;            // 0..63
        const int part = tid & 3;            // 32-col quarter of 128
        const float ndi = ndi_s[row];
        const float* cr = Csm + row * 136 + part * 32;
        const float* nj_ = ndj_s + part * 32;
        float* orow = out + ((size_t)(b * Sn + m0 + row)) * Sn + n0 + part * 32;
#pragma unroll
        for (int q = 0; q < 8; q++) {
            float4 cv = ((const float4*)cr)[q];
            float4 v;
            v.x = ndi + nj_[4 * q + 0] - 2.0f * cv.x;
            v.y = ndi + nj_[4 * q + 1] - 2.0f * cv.y;
            v.z = ndi + nj_[4 * q + 2] - 2.0f * cv.z;
            v.w = ndi + nj_[4 * q + 3] - 2.0f * cv.w;
            ((float4*)orow)[q] = v;
        }
    }

    // Mirror tile (transpose) for strictly-below-diagonal coverage
    if (mi < 2 * nj) {
        const int jj = tid >> 1;             // 0..127 (mirror row = n-index)
        const int half = tid & 1;            // ii half: 32 cols
        const float ndjv = ndj_s[jj];
        float* orow = out + ((size_t)(b * Sn + n0 + jj)) * Sn + m0 + half * 32;
#pragma unroll
        for (int q = 0; q < 8; q++) {
            float4 v;
            const int ii = half * 32 + q * 4;
            v.x = ndjv + ndi_s[ii + 0] - 2.0f * Csm[(ii + 0) * 136 + jj];
            v.y = ndjv + ndi_s[ii + 1] - 2.0f * Csm[(ii + 1) * 136 + jj];
            v.z = ndjv + ndi_s[ii + 2] - 2.0f * Csm[(ii + 2) * 136 + jj];
            v.w = ndjv + ndi_s[ii + 3] - 2.0f * Csm[(ii + 3) * 136 + jj];
            ((float4*)orow)[q] = v;
        }
    }
}

// ---------------------------------------------------------------------------
extern "C" void kernel_launch(void* const* d_in, const int* in_sizes, int n_in,
                              void* d_out, int out_size) {
    const float* E  = (const float*)d_in[0];
    const float* Wd = (const float*)d_in[1];
    const float* Wz = (const float*)d_in[2];
    float* out = (float*)d_out;

    cudaFuncSetAttribute(gemm1_k, cudaFuncAttributeMaxDynamicSharedMemorySize, SMEM1);
    cudaFuncSetAttribute(gemm2_k, cudaFuncAttributeMaxDynamicSharedMemorySize, SMEM2);

    gemm1_k<<<dim3(2, Mtot / 64), 256, SMEM1>>>(E, Wd, Wz, out + (size_t)Bn * Sn * Sn);
    gemm2_k<<<dim3(20, 1, Bn), 256, SMEM2>>>(out);
}

// round 15
// speedup vs baseline: 1.6176x; 1.6176x over previous
#include <cuda_runtime.h>
#include <cuda_bf16.h>
#include <mma.h>
#include <cstdint>

using namespace nvcuda;

// B=8, S=512, D=768, R=128
//   P = E @ [Wd;Wz]^T ; distances[b,i,j] = nd_i + nd_j - 2<Pd_i,Pd_j>; depths = ||Pz||^2
// WMMA bf16 m16n16k16 (plain sm_103 target: no tcgen05).
// gemm1: 2-term split (Eh*Wh + Eh*Wl); gemm2: 2-term (Ph*Ph + Ph*Pl), full output.
// Combined rel err ~3.7e-4 < 1e-3 threshold.

static constexpr int Bn = 8;
static constexpr int Sn = 512;
static constexpr int Dn = 768;
static constexpr int Mtot = Bn * Sn;      // 4096

// Scratch
__device__ __align__(256) __nv_bfloat16 g_Ehi[Mtot * Dn];  // E hi only
__device__ __align__(256) __nv_bfloat16 g_Whi[256 * Dn];   // rows 0-127 Wd, 128-255 Wz
__device__ __align__(256) __nv_bfloat16 g_Wlo[256 * Dn];
__device__ __align__(256) __nv_bfloat16 g_Phi[Mtot * 128]; // dist projection hi
__device__ __align__(256) __nv_bfloat16 g_Plo[Mtot * 128]; // dist projection lo
__device__ float g_nd[Mtot];

__device__ __forceinline__ uint32_t smem_u32(const void* p) {
    return (uint32_t)__cvta_generic_to_shared(p);
}
__device__ __forceinline__ void cp16(uint32_t dst, const void* src) {
    asm volatile("cp.async.cg.shared.global [%0], [%1], 16;"
                 :: "r"(dst), "l"(__cvta_generic_to_global(src)) : "memory");
}
__device__ __forceinline__ void cp_commit() {
    asm volatile("cp.async.commit_group;" ::: "memory");
}
template <int N> __device__ __forceinline__ void cp_wait() {
    asm volatile("cp.async.wait_group %0;" :: "n"(N) : "memory");
}
__device__ __forceinline__ void split2(float a, float b, uint32_t& h2, uint32_t& l2) {
    __nv_bfloat16 ha = __float2bfloat16(a), hb = __float2bfloat16(b);
    float ra = a - __bfloat162float(ha);
    float rb = b - __bfloat162float(hb);
    __nv_bfloat16 la = __float2bfloat16(ra), lb = __float2bfloat16(rb);
    h2 = (uint32_t)__bfloat16_as_ushort(ha) | ((uint32_t)__bfloat16_as_ushort(hb) << 16);
    l2 = (uint32_t)__bfloat16_as_ushort(la) | ((uint32_t)__bfloat16_as_ushort(lb) << 16);
}
__device__ __forceinline__ uint32_t pack_hi2(float a, float b) {
    return (uint32_t)__bfloat16_as_ushort(__float2bfloat16(a)) |
           ((uint32_t)__bfloat16_as_ushort(__float2bfloat16(b)) << 16);
}

typedef wmma::fragment<wmma::matrix_a, 16, 16, 16, __nv_bfloat16, wmma::row_major> FragA;
typedef wmma::fragment<wmma::matrix_b, 16, 16, 16, __nv_bfloat16, wmma::col_major> FragB;
typedef wmma::fragment<wmma::accumulator, 16, 16, 16, float> FragC;

// ---------------------------------------------------------------------------
// Prepass: E fp32 -> bf16 hi only; W (Wd|Wz) fp32 -> bf16 hi/lo.
// E-threads process 2 independent pairs (4 outstanding LDG.128, MLP=4).
// ---------------------------------------------------------------------------
static constexpr int E4 = (Mtot * Dn) / 4;    // 786432 float4 in E
static constexpr int E8 = E4 / 2;             // 393216 uint4 outputs
static constexpr int E16 = E8 / 2;            // 196608 E-threads (2 outputs each)
static constexpr int W4 = (128 * Dn) / 4;     // 24576 float4 per W matrix
static constexpr int W8 = W4;                 // 24576 W-threads
static constexpr int TOTT = E16 + W8;         // 221184 = 864 * 256

__global__ __launch_bounds__(256) void split_kernel(const float4* __restrict__ Ein,
                                                    const float4* __restrict__ Wd,
                                                    const float4* __restrict__ Wz) {
    const int idx = blockIdx.x * 256 + threadIdx.x;
    if (idx >= TOTT) return;
    if (idx < E16) {
        const int p0 = idx, p1 = idx + E16;
        float4 a0 = Ein[2 * p0];
        float4 a1 = Ein[2 * p0 + 1];
        float4 b0 = Ein[2 * p1];
        float4 b1 = Ein[2 * p1 + 1];
        uint4 h0, h1;
        h0.x = pack_hi2(a0.x, a0.y); h0.y = pack_hi2(a0.z, a0.w);
        h0.z = pack_hi2(a1.x, a1.y); h0.w = pack_hi2(a1.z, a1.w);
        h1.x = pack_hi2(b0.x, b0.y); h1.y = pack_hi2(b0.z, b0.w);
        h1.z = pack_hi2(b1.x, b1.y); h1.w = pack_hi2(b1.z, b1.w);
        ((uint4*)g_Ehi)[p0] = h0;
        ((uint4*)g_Ehi)[p1] = h1;
    } else {
        const int w = idx - E16;
        const int f = 2 * w;
        float4 v0, v1;
        if (f < W4) { v0 = Wd[f]; v1 = Wd[f + 1]; }
        else        { v0 = Wz[f - W4]; v1 = Wz[f - W4 + 1]; }
        uint4 h, l;
        split2(v0.x, v0.y, h.x, l.x);
        split2(v0.z, v0.w, h.y, l.y);
        split2(v1.x, v1.y, h.z, l.z);
        split2(v1.z, v1.w, h.w, l.w);
        ((uint4*)g_Whi)[w] = h;
        ((uint4*)g_Wlo)[w] = l;
    }
}

// ---------------------------------------------------------------------------
// GEMM1 (unchanged from R12): BM=64, BN=128, BK=64, 256 threads (8 warps 2x4).
// 2-term: Eh*(Wh + Wl). grid = (2 ntiles [dist|depth], 64 mtiles), dbl-buffered.
// Epilogue: row norms + Phi/Plo split (dist) / depths (depth) inline.
// ---------------------------------------------------------------------------
static constexpr int P1 = 72;
static constexpr int A1SZ = 64 * P1;                 // A hi only
static constexpr int B1SZ = 128 * P1;
static constexpr int BUF1 = A1SZ + 2 * B1SZ;         // 23040 elems
static constexpr int SMEM1 = 2 * BUF1 * 2;           // 92160 B

__global__ __launch_bounds__(256, 1) void gemm1_k(float* __restrict__ depths_out) {
    extern __shared__ __align__(16) char sm[];
    __nv_bfloat16* base = (__nv_bfloat16*)sm;

    const int tid = threadIdx.x;
    const int wid = tid >> 5;
    const int wm = wid >> 2, wn = wid & 3;
    const int nt = blockIdx.x;           // 0: dist, 1: depth
    const int m0 = blockIdx.y * 64;
    const int nrow0 = nt * 128;

    const int qrow = tid >> 3, qc8 = (tid & 7) * 8;  // 32 rows per pass

    auto load_chunk = [&](int c, int buf) {
        const int k0 = c * 64;
        __nv_bfloat16* Ah = base + buf * BUF1;
        __nv_bfloat16* Bh = Ah + A1SZ;
        __nv_bfloat16* Bl = Bh + B1SZ;
        const uint32_t sAh = smem_u32(Ah), sBh = smem_u32(Bh), sBl = smem_u32(Bl);
#pragma unroll
        for (int i = 0; i < 2; i++) {                // A: 64 rows x 64 cols (hi)
            const int r = qrow + i * 32;
            const uint32_t d = (uint32_t)(r * P1 + qc8) * 2;
            cp16(sAh + d, g_Ehi + (size_t)(m0 + r) * Dn + k0 + qc8);
        }
#pragma unroll
        for (int i = 0; i < 4; i++) {                // B: 128 rows x 64 cols hi+lo
            const int r = qrow + i * 32;
            const uint32_t d = (uint32_t)(r * P1 + qc8) * 2;
            const size_t s = (size_t)(nrow0 + r) * Dn + k0 + qc8;
            cp16(sBh + d, g_Whi + s);
            cp16(sBl + d, g_Wlo + s);
        }
        cp_commit();
    };

    FragC acc[2][2];
#pragma unroll
    for (int i = 0; i < 2; i++)
#pragma unroll
        for (int j = 0; j < 2; j++) wmma::fill_fragment(acc[i][j], 0.0f);

    load_chunk(0, 0);
    for (int c = 0; c < 12; c++) {
        if (c < 11) { load_chunk(c + 1, (c + 1) & 1); cp_wait<1>(); }
        else cp_wait<0>();
        __syncthreads();

        const __nv_bfloat16* Ah = base + (c & 1) * BUF1;
        const __nv_bfloat16* Bh = Ah + A1SZ;
        const __nv_bfloat16* Bl = Bh + B1SZ;
#pragma unroll
        for (int kk = 0; kk < 64; kk += 16) {
            FragA ah[2];
            FragB bh[2], bl[2];
#pragma unroll
            for (int f = 0; f < 2; f++) {
                wmma::load_matrix_sync(ah[f], Ah + (wm * 32 + f * 16) * P1 + kk, P1);
                const int n = wn * 32 + f * 16;
                wmma::load_matrix_sync(bh[f], Bh + n * P1 + kk, P1);
                wmma::load_matrix_sync(bl[f], Bl + n * P1 + kk, P1);
            }
#pragma unroll
            for (int i = 0; i < 2; i++)
#pragma unroll
                for (int j = 0; j < 2; j++) {
                    wmma::mma_sync(acc[i][j], ah[i], bh[j], acc[i][j]);
                    wmma::mma_sync(acc[i][j], ah[i], bl[j], acc[i][j]);
                }
        }
        __syncthreads();
    }

    // Epilogue: stage fp32 tile, norms + split (dist) / depths (depth)
    float* Csm = (float*)sm;                         // [64][136]
#pragma unroll
    for (int i = 0; i < 2; i++)
#pragma unroll
        for (int j = 0; j < 2; j++)
            wmma::store_matrix_sync(Csm + (wm * 32 + i * 16) * 136 + wn * 32 + j * 16,
                                    acc[i][j], 136, wmma::mem_row_major);
    __syncthreads();

    const int row = tid >> 2;            // 0..63
    const int part = tid & 3;            // 32-col quarter
    const float* cr = Csm + row * 136 + part * 32;
    float4 vv[8];
    float norm = 0.0f;
#pragma unroll
    for (int q = 0; q < 8; q++) {
        vv[q] = ((const float4*)cr)[q];
        norm += vv[q].x * vv[q].x + vv[q].y * vv[q].y +
                vv[q].z * vv[q].z + vv[q].w * vv[q].w;
    }
    norm += __shfl_xor_sync(0xffffffffu, norm, 1);
    norm += __shfl_xor_sync(0xffffffffu, norm, 2);

    const int grow = m0 + row;
    if (nt == 0) {
        uint2* dh = (uint2*)(g_Phi + (size_t)grow * 128 + part * 32);
        uint2* dl = (uint2*)(g_Plo + (size_t)grow * 128 + part * 32);
#pragma unroll
        for (int q = 0; q < 8; q++) {
            uint32_t h0, l0, h1, l1;
            split2(vv[q].x, vv[q].y, h0, l0);
            split2(vv[q].z, vv[q].w, h1, l1);
            dh[q] = make_uint2(h0, h1);
            dl[q] = make_uint2(l0, l1);
        }
        if (part == 0) g_nd[grow] = norm;
    } else {
        if (part == 0) depths_out[grow] = norm;
    }
}

// ---------------------------------------------------------------------------
// GEMM2: per-batch Gram (2-term) + distance epilogue, FULL output.
// BM=64, BN=64, BK=64 x2 dbl-buffered. 128 threads (4 warps 2x2, warp 32x32).
// smem 55KB -> occupancy 4. grid = (8, 8, 8) = 512 CTAs.
// ---------------------------------------------------------------------------
static constexpr int P2 = 72;
static constexpr int T2SZ = 64 * P2;                 // one 64-row tile (elems)
static constexpr int BUF2 = 3 * T2SZ;                // Ah, Bh, Bl = 13824 elems
static constexpr int SMEM2 = 2 * BUF2 * 2;           // 55296 B

__global__ __launch_bounds__(128, 4) void gemm2_k(float* __restrict__ out) {
    extern __shared__ __align__(16) char sm[];
    __nv_bfloat16* base = (__nv_bfloat16*)sm;
    __shared__ float ndi_s[64];
    __shared__ float ndj_s[64];

    const int tid = threadIdx.x;
    const int wid = tid >> 5;
    const int wm = wid >> 1, wn = wid & 1;           // 2x2 warp grid
    const int b = blockIdx.z;
    const int m0 = blockIdx.y * 64;
    const int n0 = blockIdx.x * 64;
    const size_t pbase = (size_t)b * Sn * 128;

    const float* __restrict__ ndb = g_nd + (size_t)b * Sn;
    if (tid < 64) ndi_s[tid] = ndb[m0 + tid];
    else ndj_s[tid - 64] = ndb[n0 + tid - 64];

    const int qrow = tid >> 3, qc8 = (tid & 7) * 8;  // 16 rows per pass

    auto load_chunk = [&](int c, int buf) {
        const int k0 = c * 64;
        __nv_bfloat16* Ah = base + buf * BUF2;
        __nv_bfloat16* Bh = Ah + T2SZ;
        __nv_bfloat16* Bl = Bh + T2SZ;
        const uint32_t sAh = smem_u32(Ah), sBh = smem_u32(Bh), sBl = smem_u32(Bl);
#pragma unroll
        for (int i = 0; i < 4; i++) {                // 64 rows: A hi, B hi, B lo
            const int r = qrow + i * 16;
            const uint32_t d = (uint32_t)(r * P2 + qc8) * 2;
            cp16(sAh + d, g_Phi + pbase + (size_t)(m0 + r) * 128 + k0 + qc8);
            const size_t s = pbase + (size_t)(n0 + r) * 128 + k0 + qc8;
            cp16(sBh + d, g_Phi + s);
            cp16(sBl + d, g_Plo + s);
        }
        cp_commit();
    };

    FragC acc[2][2];
#pragma unroll
    for (int i = 0; i < 2; i++)
#pragma unroll
        for (int j = 0; j < 2; j++) wmma::fill_fragment(acc[i][j], 0.0f);

    load_chunk(0, 0);
    for (int c = 0; c < 2; c++) {
        if (c < 1) { load_chunk(1, 1); cp_wait<1>(); }
        else cp_wait<0>();
        __syncthreads();

        const __nv_bfloat16* Ah = base + (c & 1) * BUF2;
        const __nv_bfloat16* Bh = Ah + T2SZ;
        const __nv_bfloat16* Bl = Bh + T2SZ;
#pragma unroll
        for (int kk = 0; kk < 64; kk += 16) {
            FragA ah[2];
            FragB bh[2], bl[2];
#pragma unroll
            for (int f = 0; f < 2; f++) {
                wmma::load_matrix_sync(ah[f], Ah + (wm * 32 + f * 16) * P2 + kk, P2);
                const int n = wn * 32 + f * 16;
                wmma::load_matrix_sync(bh[f], Bh + n * P2 + kk, P2);
                wmma::load_matrix_sync(bl[f], Bl + n * P2 + kk, P2);
            }
#pragma unroll
            for (int i = 0; i < 2; i++)
#pragma unroll
                for (int j = 0; j < 2; j++) {
                    wmma::mma_sync(acc[i][j], ah[i], bh[j], acc[i][j]);
                    wmma::mma_sync(acc[i][j], ah[i], bl[j], acc[i][j]);
                }
        }
        __syncthreads();
    }

    // Stage fp32 Gram, fused distance epilogue
    float* Csm = (float*)sm;                              // [64][72]
#pragma unroll
    for (int i = 0; i < 2; i++)
#pragma unroll
        for (int j = 0; j < 2; j++)
            wmma::store_matrix_sync(Csm + (wm * 32 + i * 16) * 72 + wn * 32 + j * 16,
                                    acc[i][j], 72, wmma::mem_row_major);
    __syncthreads();

    const int row = tid >> 1;            // 0..63
    const int part = tid & 1;            // 32-col half of 64
    const float ndi = ndi_s[row];
    const float* cr = Csm + row * 72 + part * 32;
    const float* nj = ndj_s + part * 32;
    float* orow = out + ((size_t)(b * Sn + m0 + row)) * Sn + n0 + part * 32;
#pragma unroll
    for (int q = 0; q < 8; q++) {
        float4 cv = ((const float4*)cr)[q];
        float4 v;
        v.x = ndi + nj[4 * q + 0] - 2.0f * cv.x;
        v.y = ndi + nj[4 * q + 1] - 2.0f * cv.y;
        v.z = ndi + nj[4 * q + 2] - 2.0f * cv.z;
        v.w = ndi + nj[4 * q + 3] - 2.0f * cv.w;
        ((float4*)orow)[q] = v;
    }
}

// ---------------------------------------------------------------------------
extern "C" void kernel_launch(void* const* d_in, const int* in_sizes, int n_in,
                              void* d_out, int out_size) {
    const float4* E  = (const float4*)d_in[0];
    const float4* Wd = (const float4*)d_in[1];
    const float4* Wz = (const float4*)d_in[2];
    float* out = (float*)d_out;

    cudaFuncSetAttribute(gemm1_k, cudaFuncAttributeMaxDynamicSharedMemorySize, SMEM1);
    cudaFuncSetAttribute(gemm2_k, cudaFuncAttributeMaxDynamicSharedMemorySize, SMEM2);

    split_kernel<<<TOTT / 256, 256>>>(E, Wd, Wz);
    gemm1_k<<<dim3(2, Mtot / 64), 256, SMEM1>>>(out + (size_t)Bn * Sn * Sn);
    gemm2_k<<<dim3(Sn / 64, Sn / 64, Bn), 128, SMEM2>>>(out);
}